// round 9
// baseline (speedup 1.0000x reference)
#include <cuda_runtime.h>
#include <cuda_bf16.h>
#include <cuda_fp16.h>
#include <math_constants.h>
#include <cstdint>

#define N_NODES 50000
#define N_EDGES 800000
#define D_IN 128
#define D_H 128
#define D_OUT 32

// ---------------- scratch (device globals; no allocation allowed) ----------------
__device__ int    g_cnt[N_NODES];
__device__ int    g_row_ptr[N_NODES + 1];
__device__ int    g_rank[N_EDGES];
__device__ int    g_col[N_EDGES];
__device__ float  g_agg[(size_t)N_NODES * D_H];
__device__ float  g_h[(size_t)N_NODES * D_H];
__device__ __half g_x16[(size_t)N_NODES * D_H];
__device__ __half g_h16[(size_t)N_NODES * D_H];
__device__ float  g_B1t[128 * 256];   // layer-1 weights [N=128][K=256] K-major, tf32-rounded
__device__ float  g_B2t[32 * 256];    // layer-2 weights [N=32][K=256]  K-major, tf32-rounded
__device__ float  g_colsum[D_H];
__device__ float  g_colsumsq[D_H];

__device__ __forceinline__ float f2tf32(float x) {
    float r;
    asm("cvt.rna.tf32.f32 %0, %1;" : "=f"(r) : "f"(x));
    return r;
}

// ---------------- setup: zero counters/stats + prepack both weight blocks ----------------
__global__ void setup_kernel(const float* __restrict__ Wl1, const float* __restrict__ Wr1,
                             const float* __restrict__ Wl2, const float* __restrict__ Wr2) {
    int i = blockIdx.x * blockDim.x + threadIdx.x;
    if (i < N_NODES) g_cnt[i] = 0;
    if (i < D_H) { g_colsum[i] = 0.f; g_colsumsq[i] = 0.f; }
    if (i < 128 * 256) {
        int n = i / 256, k = i % 256;
        float v = (k < 128) ? Wl1[n * 128 + k] : Wr1[n * 128 + (k - 128)];
        g_B1t[i] = f2tf32(v);
    }
    if (i < 32 * 256) {
        int n = i / 256, k = i % 256;
        float v = (k < 128) ? Wl2[n * 128 + k] : Wr2[n * 128 + (k - 128)];
        g_B2t[i] = f2tf32(v);
    }
}

// ---------------- CSR build ----------------
// histogram + per-edge rank (2 edges/thread for MLP); also converts x -> fp16
__global__ void hist_kernel(const int* __restrict__ dst, int E,
                            const float* __restrict__ x, int total4, int T) {
    int t = blockIdx.x * blockDim.x + threadIdx.x;
    int e0 = t * 2;
    if (e0 < E) {
        int d0 = __ldg(&dst[e0]);
        if (e0 + 1 < E) {
            int d1 = __ldg(&dst[e0 + 1]);
            g_rank[e0] = atomicAdd(&g_cnt[d0], 1);
            g_rank[e0 + 1] = atomicAdd(&g_cnt[d1], 1);
        } else {
            g_rank[e0] = atomicAdd(&g_cnt[d0], 1);
        }
    }
    const float4* X4 = reinterpret_cast<const float4*>(x);
    for (int idx = t; idx < total4; idx += T) {
        float4 v = __ldg(&X4[idx]);
        __half2 a = __floats2half2_rn(v.x, v.y);
        __half2 b = __floats2half2_rn(v.z, v.w);
        uint2 o;
        o.x = *reinterpret_cast<uint32_t*>(&a);
        o.y = *reinterpret_cast<uint32_t*>(&b);
        *reinterpret_cast<uint2*>(&g_x16[(size_t)idx * 4]) = o;
    }
}

__global__ void scan_kernel(int n) {
    __shared__ int s[1024];
    const int PER = (n + 1023) / 1024;
    int t = threadIdx.x;
    int start = t * PER;
    int end = min(start + PER, n);
    int sum = 0;
    for (int i = start; i < end; i++) sum += g_cnt[i];
    s[t] = sum;
    __syncthreads();
    #pragma unroll
    for (int d = 1; d < 1024; d <<= 1) {
        int u = (t >= d) ? s[t - d] : 0;
        __syncthreads();
        s[t] += u;
        __syncthreads();
    }
    int run = s[t] - sum;
    for (int i = start; i < end; i++) {
        int c = g_cnt[i];
        g_row_ptr[i] = run;
        run += c;
    }
    if (t == 1023) g_row_ptr[n] = run;
}

// atomic-free scatter, 2 edges/thread for MLP
__global__ void scatter_kernel(const int* __restrict__ src, const int* __restrict__ dst, int E) {
    int t = blockIdx.x * blockDim.x + threadIdx.x;
    int e0 = t * 2;
    if (e0 + 1 < E) {
        int d0 = __ldg(&dst[e0]),      d1 = __ldg(&dst[e0 + 1]);
        int r0 = __ldg(&g_rank[e0]),   r1 = __ldg(&g_rank[e0 + 1]);
        int s0 = __ldg(&src[e0]),      s1 = __ldg(&src[e0 + 1]);
        int p0 = __ldg(&g_row_ptr[d0]), p1 = __ldg(&g_row_ptr[d1]);
        g_col[p0 + r0] = s0;
        g_col[p1 + r1] = s1;
    } else if (e0 < E) {
        int d0 = __ldg(&dst[e0]);
        g_col[__ldg(&g_row_ptr[d0]) + __ldg(&g_rank[e0])] = __ldg(&src[e0]);
    }
}

// ---------------- scatter-max aggregation over fp16 source: one warp per node ----------------
// Output pre-rounded to tf32 (feeds GEMM A0 half directly).
template <bool XFORM>
__global__ void agg16_kernel(const __half* __restrict__ X16, float* __restrict__ AGG, int nNodes,
                             const float* __restrict__ gamma, const float* __restrict__ beta,
                             float invM) {
    __shared__ float s_sc[XFORM ? 128 : 1];
    __shared__ float s_sh[XFORM ? 128 : 1];
    int tid = threadIdx.x;
    if (XFORM) {
        if (tid < 128) {
            float mean = g_colsum[tid] * invM;
            float var = g_colsumsq[tid] * invM - mean * mean;
            float sc = gamma[tid] * rsqrtf(var + 1e-5f);
            s_sc[tid] = sc;
            s_sh[tid] = beta[tid] - mean * sc;
        }
        __syncthreads();
    }
    int warp = (blockIdx.x * blockDim.x + tid) >> 5;
    int lane = tid & 31;
    if (warp >= nNodes) return;
    int s = g_row_ptr[warp];
    int e = g_row_ptr[warp + 1];
    float4 sc, sh;
    if (XFORM) {
        sc = *reinterpret_cast<const float4*>(&s_sc[lane * 4]);
        sh = *reinterpret_cast<const float4*>(&s_sh[lane * 4]);
    }
    float4 m = make_float4(-CUDART_INF_F, -CUDART_INF_F, -CUDART_INF_F, -CUDART_INF_F);
    const uint2* X2 = reinterpret_cast<const uint2*>(X16);
    #pragma unroll 4
    for (int i = s; i < e; i++) {
        int src = __ldg(&g_col[i]);
        uint2 p = __ldg(&X2[(size_t)src * 32 + lane]);
        __half2 h0 = *reinterpret_cast<const __half2*>(&p.x);
        __half2 h1 = *reinterpret_cast<const __half2*>(&p.y);
        float2 f0 = __half22float2(h0);
        float2 f1 = __half22float2(h1);
        if (XFORM) {
            f0.x = fmaxf(fmaf(f0.x, sc.x, sh.x), 0.f);
            f0.y = fmaxf(fmaf(f0.y, sc.y, sh.y), 0.f);
            f1.x = fmaxf(fmaf(f1.x, sc.z, sh.z), 0.f);
            f1.y = fmaxf(fmaf(f1.y, sc.w, sh.w), 0.f);
        }
        m.x = fmaxf(m.x, f0.x); m.y = fmaxf(m.y, f0.y);
        m.z = fmaxf(m.z, f1.x); m.w = fmaxf(m.w, f1.y);
    }
    if (s == e) m = make_float4(0.f, 0.f, 0.f, 0.f);
    m.x = f2tf32(m.x); m.y = f2tf32(m.y); m.z = f2tf32(m.z); m.w = f2tf32(m.w);
    reinterpret_cast<float4*>(AGG)[(size_t)warp * 32 + lane] = m;
}

// ---------------- common mma helper ----------------
__device__ __forceinline__ void mma_tf32(float* d, const uint32_t* a, const uint32_t* b) {
    asm volatile(
        "mma.sync.aligned.m16n8k8.row.col.f32.tf32.tf32.f32 "
        "{%0,%1,%2,%3}, {%4,%5,%6,%7}, {%8,%9}, {%0,%1,%2,%3};"
        : "+f"(d[0]), "+f"(d[1]), "+f"(d[2]), "+f"(d[3])
        : "r"(a[0]), "r"(a[1]), "r"(a[2]), "r"(a[3]), "r"(b[0]), "r"(b[1]));
}

// ---------------- layer-1 GEMM via mma.sync tf32, streamed B chunks ----------------
// C[M,128] = [A0 | A1] @ B1t^T + bias; fused BN column stats; also writes h in fp16.
// smem: Bs[128][68] + As[128][68] + stats -> ~70KB -> 2 CTAs/SM.
#define G1_STRIDE 68
#define G1_SMEM_BYTES ((128 * G1_STRIDE * 2 + 256) * 4)

__global__ __launch_bounds__(256, 2)
void gemm1_mma_kernel(const float* __restrict__ A0, const float* __restrict__ A1,
                      const float* __restrict__ Bt, const float* __restrict__ bias,
                      float* __restrict__ C, int M) {
    extern __shared__ float sm[];
    float* Bs   = sm;                        // [128][68] current B chunk
    float* As   = sm + 128 * G1_STRIDE;      // [128][68] current A chunk
    float* ssum = As + 128 * G1_STRIDE;      // [128]
    float* ssq  = ssum + 128;                // [128]

    int tid = threadIdx.x;
    int lane = tid & 31;
    int wid = tid >> 5;
    int warpM = wid & 3;
    int warpN = wid >> 2;
    int g = lane >> 2;
    int tig = lane & 3;
    int m0 = blockIdx.x * 128;

    if (tid < 128) { ssum[tid] = 0.f; ssq[tid] = 0.f; }

    float acc[2][8][4];
    #pragma unroll
    for (int mi = 0; mi < 2; mi++)
        #pragma unroll
        for (int ni = 0; ni < 8; ni++)
            #pragma unroll
            for (int q = 0; q < 4; q++) acc[mi][ni][q] = 0.f;

    const float4* Bt4 = reinterpret_cast<const float4*>(Bt);

    #pragma unroll 1
    for (int kc = 0; kc < 4; kc++) {
        __syncthreads();   // previous compute done, smem free
        // B chunk: rows n=0..127, chunk-local cols 0..63 (16 float4/row)
        #pragma unroll
        for (int j = 0; j < 8; j++) {
            int i = tid + 256 * j;
            int n = i >> 4, k4 = i & 15;
            float4 v = __ldg(&Bt4[n * 64 + kc * 16 + k4]);
            *reinterpret_cast<float4*>(&Bs[n * G1_STRIDE + k4 * 4]) = v;
        }
        // A chunk: kc<2 from A0 (pre-rounded tf32), kc>=2 from A1 (needs cvt)
        {
            const float4* S4 = reinterpret_cast<const float4*>(kc < 2 ? A0 : A1);
            int cbase = (kc & 1) * 16;
            #pragma unroll
            for (int j = 0; j < 8; j++) {
                int i = tid + 256 * j;
                int r = i >> 4, k4 = i & 15;
                int row = m0 + r;
                float4 v = (row < M) ? __ldg(&S4[(size_t)row * 32 + cbase + k4])
                                     : make_float4(0.f, 0.f, 0.f, 0.f);
                if (kc >= 2) {
                    v.x = f2tf32(v.x); v.y = f2tf32(v.y);
                    v.z = f2tf32(v.z); v.w = f2tf32(v.w);
                }
                *reinterpret_cast<float4*>(&As[r * G1_STRIDE + k4 * 4]) = v;
            }
        }
        __syncthreads();

        #pragma unroll
        for (int ks = 0; ks < 8; ks++) {
            int k = ks * 8;
            uint32_t afr[2][4];
            #pragma unroll
            for (int mi = 0; mi < 2; mi++) {
                int r = warpM * 32 + mi * 16 + g;
                afr[mi][0] = __float_as_uint(As[r * G1_STRIDE + k + tig]);
                afr[mi][1] = __float_as_uint(As[(r + 8) * G1_STRIDE + k + tig]);
                afr[mi][2] = __float_as_uint(As[r * G1_STRIDE + k + tig + 4]);
                afr[mi][3] = __float_as_uint(As[(r + 8) * G1_STRIDE + k + tig + 4]);
            }
            uint32_t bfr[8][2];
            #pragma unroll
            for (int ni = 0; ni < 8; ni++) {
                int n = warpN * 64 + ni * 8 + g;
                bfr[ni][0] = __float_as_uint(Bs[n * G1_STRIDE + k + tig]);
                bfr[ni][1] = __float_as_uint(Bs[n * G1_STRIDE + k + tig + 4]);
            }
            #pragma unroll
            for (int mi = 0; mi < 2; mi++)
                #pragma unroll
                for (int ni = 0; ni < 8; ni++)
                    mma_tf32(acc[mi][ni], afr[mi], bfr[ni]);
        }
    }

    // epilogue: bias + store fp32 & fp16 + fused BN column stats
    #pragma unroll
    for (int ni = 0; ni < 8; ni++) {
        int col = warpN * 64 + ni * 8 + tig * 2;
        float b0 = bias[col], b1 = bias[col + 1];
        float s0 = 0.f, q0 = 0.f, s1 = 0.f, q1 = 0.f;
        #pragma unroll
        for (int mi = 0; mi < 2; mi++) {
            int r0 = m0 + warpM * 32 + mi * 16 + g;
            if (r0 < M) {
                float v0 = acc[mi][ni][0] + b0;
                float v1 = acc[mi][ni][1] + b1;
                *reinterpret_cast<float2*>(&C[(size_t)r0 * 128 + col]) = make_float2(v0, v1);
                __half2 hh = __floats2half2_rn(v0, v1);
                *reinterpret_cast<uint32_t*>(&g_h16[(size_t)r0 * 128 + col]) =
                    *reinterpret_cast<uint32_t*>(&hh);
                s0 += v0; q0 += v0 * v0; s1 += v1; q1 += v1 * v1;
            }
            int r1 = r0 + 8;
            if (r1 < M) {
                float v2 = acc[mi][ni][2] + b0;
                float v3 = acc[mi][ni][3] + b1;
                *reinterpret_cast<float2*>(&C[(size_t)r1 * 128 + col]) = make_float2(v2, v3);
                __half2 hh = __floats2half2_rn(v2, v3);
                *reinterpret_cast<uint32_t*>(&g_h16[(size_t)r1 * 128 + col]) =
                    *reinterpret_cast<uint32_t*>(&hh);
                s0 += v2; q0 += v2 * v2; s1 += v3; q1 += v3 * v3;
            }
        }
        atomicAdd(&ssum[col], s0); atomicAdd(&ssq[col], q0);
        atomicAdd(&ssum[col + 1], s1); atomicAdd(&ssq[col + 1], q1);
    }
    __syncthreads();
    if (tid < 128) {
        atomicAdd(&g_colsum[tid], ssum[tid]);
        atomicAdd(&g_colsumsq[tid], ssq[tid]);
    }
}

// ---------------- layer-2 GEMM via mma.sync tf32 (N=32) ----------------
#define G2_BSTRIDE 260
#define G2_ASTRIDE 68
#define G2_SMEM_BYTES ((32 * G2_BSTRIDE + 128 * G2_ASTRIDE + 256) * 4)

__global__ __launch_bounds__(256)
void gemm2_mma_kernel(const float* __restrict__ A0, const float* __restrict__ A1,
                      const float* __restrict__ Bt, const float* __restrict__ bias,
                      const float* __restrict__ gamma, const float* __restrict__ beta,
                      float invM, float* __restrict__ C, int M) {
    extern __shared__ float sm[];
    float* Bs   = sm;                      // [32][260]
    float* As   = sm + 32 * G2_BSTRIDE;    // [128][68]
    float* s_sc = As + 128 * G2_ASTRIDE;   // [128]
    float* s_sh = s_sc + 128;              // [128]

    int tid = threadIdx.x;
    int lane = tid & 31;
    int wid = tid >> 5;
    int g = lane >> 2;
    int tig = lane & 3;
    int m0 = blockIdx.x * 128;

    if (tid < 128) {
        float mean = g_colsum[tid] * invM;
        float var = g_colsumsq[tid] * invM - mean * mean;
        float sc = gamma[tid] * rsqrtf(var + 1e-5f);
        s_sc[tid] = sc;
        s_sh[tid] = beta[tid] - mean * sc;
    }

    const float4* Bt4 = reinterpret_cast<const float4*>(Bt);
    #pragma unroll
    for (int idx = tid; idx < 32 * 64; idx += 256) {
        int n = idx >> 6, k4 = idx & 63;
        float4 v = __ldg(&Bt4[n * 64 + k4]);
        *reinterpret_cast<float4*>(&Bs[n * G2_BSTRIDE + k4 * 4]) = v;
    }

    float acc[4][4];
    #pragma unroll
    for (int ni = 0; ni < 4; ni++)
        #pragma unroll
        for (int q = 0; q < 4; q++) acc[ni][q] = 0.f;

    float4 stage[8];
    {
        const float4* S4 = reinterpret_cast<const float4*>(A0);
        #pragma unroll
        for (int j = 0; j < 8; j++) {
            int i = tid + 256 * j;
            int r = i >> 4, c4 = i & 15;
            int row = m0 + r;
            stage[j] = (row < M) ? __ldg(&S4[(size_t)row * 32 + c4])
                                 : make_float4(0.f, 0.f, 0.f, 0.f);
        }
    }

    #pragma unroll 1
    for (int kc = 0; kc < 4; kc++) {
        __syncthreads();
        #pragma unroll
        for (int j = 0; j < 8; j++) {
            int i = tid + 256 * j;
            int r = i >> 4, c4 = i & 15;
            float4 v = stage[j];
            if (kc >= 2) {  // A1 half: BN affine + ReLU + cvt
                int cb = (kc & 1) * 64 + c4 * 4;
                v.x = fmaxf(fmaf(v.x, s_sc[cb + 0], s_sh[cb + 0]), 0.f);
                v.y = fmaxf(fmaf(v.y, s_sc[cb + 1], s_sh[cb + 1]), 0.f);
                v.z = fmaxf(fmaf(v.z, s_sc[cb + 2], s_sh[cb + 2]), 0.f);
                v.w = fmaxf(fmaf(v.w, s_sc[cb + 3], s_sh[cb + 3]), 0.f);
                v.x = f2tf32(v.x); v.y = f2tf32(v.y); v.z = f2tf32(v.z); v.w = f2tf32(v.w);
            }
            *reinterpret_cast<float4*>(&As[r * G2_ASTRIDE + c4 * 4]) = v;
        }
        if (kc < 3) {
            int nc = kc + 1;
            const float4* S4 = reinterpret_cast<const float4*>(nc < 2 ? A0 : A1);
            int cbase = (nc & 1) * 16;
            #pragma unroll
            for (int j = 0; j < 8; j++) {
                int i = tid + 256 * j;
                int r = i >> 4, c4 = i & 15;
                int row = m0 + r;
                stage[j] = (row < M) ? __ldg(&S4[(size_t)row * 32 + cbase + c4])
                                     : make_float4(0.f, 0.f, 0.f, 0.f);
            }
        }
        __syncthreads();

        const float* Bkc = Bs + kc * 64;
        #pragma unroll
        for (int ks = 0; ks < 8; ks++) {
            int k = ks * 8;
            uint32_t afr[4];
            int r = wid * 16 + g;
            afr[0] = __float_as_uint(As[r * G2_ASTRIDE + k + tig]);
            afr[1] = __float_as_uint(As[(r + 8) * G2_ASTRIDE + k + tig]);
            afr[2] = __float_as_uint(As[r * G2_ASTRIDE + k + tig + 4]);
            afr[3] = __float_as_uint(As[(r + 8) * G2_ASTRIDE + k + tig + 4]);
            uint32_t bfr[4][2];
            #pragma unroll
            for (int ni = 0; ni < 4; ni++) {
                int n = ni * 8 + g;
                bfr[ni][0] = __float_as_uint(Bkc[n * G2_BSTRIDE + k + tig]);
                bfr[ni][1] = __float_as_uint(Bkc[n * G2_BSTRIDE + k + tig + 4]);
            }
            #pragma unroll
            for (int ni = 0; ni < 4; ni++)
                mma_tf32(acc[ni], afr, bfr[ni]);
        }
    }

    #pragma unroll
    for (int ni = 0; ni < 4; ni++) {
        int col = ni * 8 + tig * 2;
        float b0 = bias[col], b1 = bias[col + 1];
        int r0 = m0 + wid * 16 + g;
        if (r0 < M)
            *reinterpret_cast<float2*>(&C[(size_t)r0 * 32 + col]) =
                make_float2(acc[ni][0] + b0, acc[ni][1] + b1);
        int r1 = r0 + 8;
        if (r1 < M)
            *reinterpret_cast<float2*>(&C[(size_t)r1 * 32 + col]) =
                make_float2(acc[ni][2] + b0, acc[ni][3] + b1);
    }
}

// ---------------- launch ----------------
extern "C" void kernel_launch(void* const* d_in, const int* in_sizes, int n_in,
                              void* d_out, int out_size) {
    const float* x     = (const float*)d_in[0];
    const int*   ei    = (const int*)d_in[1];
    const float* Wl1   = (const float*)d_in[2];
    const float* bl1   = (const float*)d_in[3];
    const float* Wr1   = (const float*)d_in[4];
    const float* gamma = (const float*)d_in[5];
    const float* beta  = (const float*)d_in[6];
    const float* Wl2   = (const float*)d_in[7];
    const float* bl2   = (const float*)d_in[8];
    const float* Wr2   = (const float*)d_in[9];
    float* out = (float*)d_out;

    int M = in_sizes[0] / D_IN;       // 50000
    int E = in_sizes[1] / 2;          // 800000
    const int* src = ei;
    const int* dst = ei + E;
    float invM = 1.0f / (float)M;

    float *p_agg, *p_h, *p_B1t, *p_B2t;
    __half *p_x16, *p_h16;
    cudaGetSymbolAddress((void**)&p_agg,  g_agg);
    cudaGetSymbolAddress((void**)&p_h,    g_h);
    cudaGetSymbolAddress((void**)&p_B1t,  g_B1t);
    cudaGetSymbolAddress((void**)&p_B2t,  g_B2t);
    cudaGetSymbolAddress((void**)&p_x16,  g_x16);
    cudaGetSymbolAddress((void**)&p_h16,  g_h16);

    cudaFuncSetAttribute(gemm1_mma_kernel,
                         cudaFuncAttributeMaxDynamicSharedMemorySize, G1_SMEM_BYTES);
    cudaFuncSetAttribute(gemm2_mma_kernel,
                         cudaFuncAttributeMaxDynamicSharedMemorySize, G2_SMEM_BYTES);

    // setup + CSR build (hist also converts x -> fp16; 2 edges/thread)
    setup_kernel<<<(N_NODES + 255) / 256, 256>>>(Wl1, Wr1, Wl2, Wr2);
    {
        int T = (E + 1) / 2;
        hist_kernel<<<(T + 255) / 256, 256>>>(dst, E, x, M * 32, T);
    }
    scan_kernel<<<1, 1024>>>(M);
    scatter_kernel<<<((E + 1) / 2 + 255) / 256, 256>>>(src, dst, E);

    // layer 1: agg = scatter_max(x16) [tf32-rounded]; h = [agg|x] @ B1 + b1
    agg16_kernel<false><<<(M * 32 + 255) / 256, 256>>>(p_x16, p_agg, M, gamma, beta, invM);
    gemm1_mma_kernel<<<(M + 127) / 128, 256, G1_SMEM_BYTES>>>(p_agg, x, p_B1t, bl1, p_h, M);

    // layer 2: agg2 = scatter_max(relu(bn(h16))) [tf32-rounded]; out = [agg2 | relu(bn(h))] @ B2 + b2
    agg16_kernel<true><<<(M * 32 + 255) / 256, 256>>>(p_h16, p_agg, M, gamma, beta, invM);
    gemm2_mma_kernel<<<(M + 127) / 128, 256, G2_SMEM_BYTES>>>(p_agg, p_h, p_B2t, bl2,
                                                              gamma, beta, invM, out, M);
}